// round 6
// baseline (speedup 1.0000x reference)
#include <cuda_runtime.h>
#include <cstdint>

#define SEQ   2048
#define BATCH 4
#define NTOK  (SEQ * BATCH)      // 8192
#define DIM   1024
#define NH    16
#define HD    64

// ---------------- scratch (device globals per allocation rules) -------------
__device__ float g_xpe [NTOK * DIM];
__device__ float g_q   [NTOK * DIM];
__device__ float g_k   [NTOK * DIM];
__device__ float g_v   [NTOK * DIM];
__device__ float g_attn[NTOK * DIM];
__device__ float g_proj[NTOK * DIM];
__device__ float g_wT  [4][DIM * DIM];   // transposed weights [N,K]

// ---------------- helpers -----------------------------------------------------
__device__ __forceinline__ uint32_t smem_u32(const void* p) {
    uint32_t a;
    asm("{ .reg .u64 t; cvta.to.shared.u64 t, %1; cvt.u32.u64 %0, t; }" : "=r"(a) : "l"(p));
    return a;
}
__device__ __forceinline__ void cp16(uint32_t dst, const void* src) {
    asm volatile("cp.async.cg.shared.global [%0], [%1], 16;" :: "r"(dst), "l"(src));
}
#define CP_COMMIT() asm volatile("cp.async.commit_group;" ::: "memory")
#define CP_WAIT0()  asm volatile("cp.async.wait_group 0;" ::: "memory")
#define CP_WAIT1()  asm volatile("cp.async.wait_group 1;" ::: "memory")

// raw fp32 bits as tf32 operands (HW truncates low mantissa bits)
__device__ __forceinline__ void mma_tf32(float* d, const uint32_t* a, const uint32_t* b) {
    asm volatile(
        "mma.sync.aligned.m16n8k8.row.col.f32.tf32.tf32.f32 "
        "{%0,%1,%2,%3}, {%4,%5,%6,%7}, {%8,%9}, {%0,%1,%2,%3};\n"
        : "+f"(d[0]), "+f"(d[1]), "+f"(d[2]), "+f"(d[3])
        : "r"(a[0]), "r"(a[1]), "r"(a[2]), "r"(a[3]), "r"(b[0]), "r"(b[1]));
}

// ---------------- x + pe ----------------------------------------------------
__global__ void k_addpe(const float* __restrict__ x, const float* __restrict__ pe) {
    int idx = blockIdx.x * 256 + threadIdx.x;
    const float4* x4  = (const float4*)x;
    const float4* pe4 = (const float4*)pe;
    float4*       o4  = (float4*)g_xpe;
    int row = idx >> 8;
    int c   = idx & 255;
    int s   = row & (SEQ - 1);
    float4 a = x4[idx];
    float4 b = pe4[s * 256 + c];
    a.x += b.x; a.y += b.y; a.z += b.z; a.w += b.w;
    o4[idx] = a;
}

// ---------------- fused weight transpose (4 weights via blockIdx.z) ----------
__global__ __launch_bounds__(256) void k_transpose4(
    const float* __restrict__ w0, const float* __restrict__ w1,
    const float* __restrict__ w2, const float* __restrict__ w3)
{
    __shared__ float t[32][33];
    const float* in;
    switch (blockIdx.z) {
        case 0: in = w0; break;
        case 1: in = w1; break;
        case 2: in = w2; break;
        default: in = w3; break;
    }
    float* out = g_wT[blockIdx.z];
    int n0 = blockIdx.x * 32, k0 = blockIdx.y * 32;
    int tx = threadIdx.x & 31, ty = threadIdx.x >> 5;
    #pragma unroll
    for (int i = ty; i < 32; i += 8)
        t[i][tx] = in[(size_t)(k0 + i) * DIM + n0 + tx];
    __syncthreads();
    #pragma unroll
    for (int i = ty; i < 32; i += 8)
        out[(size_t)(n0 + i) * DIM + k0 + tx] = t[tx][i];
}

// ---------------- tf32 mma GEMM (multi-output): C[M,N] = A @ BtT + bias ------
// grid.x = nsel*8 (which = bx>>3). 128x128 CTA tile, BK=32, 8 warps, 3 CTA/SM.
#define GPAD  36
#define GTILE (128 * GPAD)
#define GSMEM (4 * GTILE * 4)              // 73728 bytes
#define NC    (DIM / 32)

__global__ __launch_bounds__(256, 3) void k_gemm_mma(
    const float* __restrict__ A,
    const float* __restrict__ Bt0, const float* __restrict__ Bt1, const float* __restrict__ Bt2,
    const float* __restrict__ b0,  const float* __restrict__ b1,  const float* __restrict__ b2,
    float* __restrict__ C0, float* __restrict__ C1, float* __restrict__ C2)
{
    extern __shared__ uint32_t sm[];
    const uint32_t smb = smem_u32(sm);
    const int tid  = threadIdx.x;
    const int lane = tid & 31;
    const int wid  = tid >> 5;
    const int wr   = wid & 3;
    const int wc   = wid >> 2;
    const int which = blockIdx.x >> 3;
    const int rowBase = blockIdx.y * 128;
    const int colBase = (blockIdx.x & 7) * 128;

    const float* Bt   = (which == 0) ? Bt0 : (which == 1) ? Bt1 : Bt2;
    const float* bias = (which == 0) ? b0  : (which == 1) ? b1  : b2;
    float*       C    = (which == 0) ? C0  : (which == 1) ? C1  : C2;

    const float* Ab = A  + (size_t)rowBase * DIM;
    const float* Bb = Bt + (size_t)colBase * DIM;

    float acc[2][8][4];
    #pragma unroll
    for (int mt = 0; mt < 2; mt++)
        #pragma unroll
        for (int nt = 0; nt < 8; nt++)
            #pragma unroll
            for (int j = 0; j < 4; j++) acc[mt][nt][j] = 0.f;

    auto copy_tile = [&](int buf, int chunk) {
        uint32_t as_ = smb + buf * 2 * GTILE * 4;
        uint32_t bs_ = as_ + GTILE * 4;
        #pragma unroll
        for (int i = 0; i < 4; i++) {
            int idx = i * 256 + tid;
            int r = idx >> 3, c4 = idx & 7;
            uint32_t off = (r * GPAD + c4 * 4) * 4;
            cp16(as_ + off, Ab + (size_t)r * DIM + chunk * 32 + c4 * 4);
            cp16(bs_ + off, Bb + (size_t)r * DIM + chunk * 32 + c4 * 4);
        }
    };
    auto compute = [&](int buf) {
        const uint32_t* as_ = sm + buf * 2 * GTILE;
        const uint32_t* bs_ = as_ + GTILE;
        #pragma unroll
        for (int kk = 0; kk < 32; kk += 8) {
            uint32_t af[2][4];
            #pragma unroll
            for (int mt = 0; mt < 2; mt++) {
                int r = wr * 32 + mt * 16 + (lane >> 2);
                int c = kk + (lane & 3);
                af[mt][0] = as_[r * GPAD + c];
                af[mt][1] = as_[(r + 8) * GPAD + c];
                af[mt][2] = as_[r * GPAD + c + 4];
                af[mt][3] = as_[(r + 8) * GPAD + c + 4];
            }
            #pragma unroll
            for (int nt = 0; nt < 8; nt++) {
                int n = wc * 64 + nt * 8 + (lane >> 2);
                uint32_t bf[2];
                bf[0] = bs_[n * GPAD + kk + (lane & 3)];
                bf[1] = bs_[n * GPAD + kk + (lane & 3) + 4];
                mma_tf32(acc[0][nt], af[0], bf);
                mma_tf32(acc[1][nt], af[1], bf);
            }
        }
    };

    copy_tile(0, 0); CP_COMMIT();
    CP_WAIT0(); __syncthreads();
    for (int c = 0; c < NC; c++) {
        int b = c & 1;
        if (c + 1 < NC) { copy_tile(b ^ 1, c + 1); CP_COMMIT(); }
        compute(b);
        CP_WAIT0(); __syncthreads();
    }

    #pragma unroll
    for (int mt = 0; mt < 2; mt++) {
        int r = rowBase + wr * 32 + mt * 16 + (lane >> 2);
        #pragma unroll
        for (int nt = 0; nt < 8; nt++) {
            int col = colBase + wc * 64 + nt * 8 + 2 * (lane & 3);
            float2 b2 = *(const float2*)&bias[col];
            float2 o0 = make_float2(acc[mt][nt][0] + b2.x, acc[mt][nt][1] + b2.y);
            float2 o1 = make_float2(acc[mt][nt][2] + b2.x, acc[mt][nt][3] + b2.y);
            *(float2*)&C[(size_t)r * DIM + col]       = o0;
            *(float2*)&C[(size_t)(r + 8) * DIM + col] = o1;
        }
    }
}

// ---------------- flash attention via mma ------------------------------------
// 256 threads / 8 warps, 128 queries per CTA; warp owns 16 q-rows.
// Single K buffer + single V buffer, pipelined via cp.async group ordering.
// Softmax in exp2 domain (scale folded with log2e).
#define AQS 68
#define AVS 72
#define OFF_Q  0
#define OFF_KK (128 * AQS)
#define OFF_VV (OFF_KK + 64 * AQS)
#define OFF_PP (OFF_VV + 64 * AVS)
#define ASMEM  ((OFF_PP + 128 * AQS) * 4)  // 105472 bytes
#define NT   (SEQ / 64)
#define SCL  0.18033688011112042f          // 0.125 * log2(e)

__global__ __launch_bounds__(256) void k_attn_mma()
{
    extern __shared__ uint32_t sm[];
    const uint32_t smb = smem_u32(sm);
    uint32_t* Qs = sm + OFF_Q;
    uint32_t* Ks = sm + OFF_KK;
    uint32_t* Vs = sm + OFF_VV;
    uint32_t* Ps = sm + OFF_PP;

    const int tid  = threadIdx.x;
    const int lane = tid & 31;
    const int wid  = tid >> 5;
    const int qt = blockIdx.x, h = blockIdx.y, b = blockIdx.z;
    const size_t qbase  = (size_t)(b * SEQ + qt * 128);
    const size_t kvbase = (size_t)(b * SEQ) * DIM + h * 64;

    auto copy_q = [&]() {
        #pragma unroll
        for (int i = 0; i < 8; i++) {
            int idx = i * 256 + tid;
            int r = idx >> 4, c4 = idx & 15;
            cp16(smb + (OFF_Q + r * AQS + c4 * 4) * 4,
                 g_q + (qbase + r) * DIM + h * 64 + c4 * 4);
        }
    };
    auto copy_k = [&](int kt) {
        #pragma unroll
        for (int i = 0; i < 4; i++) {
            int idx = i * 256 + tid;
            int r = idx >> 4, c4 = idx & 15;
            cp16(smb + (OFF_KK + r * AQS + c4 * 4) * 4,
                 g_k + kvbase + (size_t)(kt * 64 + r) * DIM + c4 * 4);
        }
    };
    auto copy_v = [&](int kt) {
        #pragma unroll
        for (int i = 0; i < 4; i++) {
            int idx = i * 256 + tid;
            int r = idx >> 4, c4 = idx & 15;
            cp16(smb + (OFF_VV + r * AVS + c4 * 4) * 4,
                 g_v + kvbase + (size_t)(kt * 64 + r) * DIM + c4 * 4);
        }
    };

    float Oa[8][4];
    #pragma unroll
    for (int nt = 0; nt < 8; nt++)
        #pragma unroll
        for (int j = 0; j < 4; j++) Oa[nt][j] = 0.f;
    float m0 = -1e30f, m1 = -1e30f, l0 = 0.f, l1 = 0.f;   // m in log2 units

    copy_q(); copy_k(0); CP_COMMIT();       // group: Q+K0
    copy_v(0); CP_COMMIT();                 // group: V0
    CP_WAIT1(); __syncthreads();            // Q + K0 ready; V0 in flight

    for (int kt = 0; kt < NT; kt++) {
        // ---- S = Q @ K^T (K[kt] resident) ----
        float Sa[8][4];
        #pragma unroll
        for (int nt = 0; nt < 8; nt++)
            #pragma unroll
            for (int j = 0; j < 4; j++) Sa[nt][j] = 0.f;
        #pragma unroll
        for (int kk = 0; kk < 64; kk += 8) {
            uint32_t af[4];
            int r = wid * 16 + (lane >> 2);
            int c = kk + (lane & 3);
            af[0] = Qs[r * AQS + c];
            af[1] = Qs[(r + 8) * AQS + c];
            af[2] = Qs[r * AQS + c + 4];
            af[3] = Qs[(r + 8) * AQS + c + 4];
            #pragma unroll
            for (int nt = 0; nt < 8; nt++) {
                int n = nt * 8 + (lane >> 2);
                uint32_t bf[2];
                bf[0] = Ks[n * AQS + kk + (lane & 3)];
                bf[1] = Ks[n * AQS + kk + (lane & 3) + 4];
                mma_tf32(Sa[nt], af, bf);
            }
        }
        __syncthreads();                     // all warps done with K[kt]
        if (kt + 1 < NT) { copy_k(kt + 1); CP_COMMIT(); }

        #pragma unroll
        for (int nt = 0; nt < 8; nt++)
            #pragma unroll
            for (int j = 0; j < 4; j++) Sa[nt][j] *= SCL;   // log2-domain scores

        // ---- online softmax (exp2 domain) ----
        float mx0 = m0, mx1 = m1;
        #pragma unroll
        for (int nt = 0; nt < 8; nt++) {
            mx0 = fmaxf(mx0, fmaxf(Sa[nt][0], Sa[nt][1]));
            mx1 = fmaxf(mx1, fmaxf(Sa[nt][2], Sa[nt][3]));
        }
        #pragma unroll
        for (int o = 1; o <= 2; o <<= 1) {
            mx0 = fmaxf(mx0, __shfl_xor_sync(0xffffffffu, mx0, o));
            mx1 = fmaxf(mx1, __shfl_xor_sync(0xffffffffu, mx1, o));
        }
        float corr0 = exp2f(m0 - mx0);
        float corr1 = exp2f(m1 - mx1);
        m0 = mx0; m1 = mx1;

        float s0 = 0.f, s1 = 0.f;
        int pr = wid * 16 + (lane >> 2);
        #pragma unroll
        for (int nt = 0; nt < 8; nt++) {
            float p00 = exp2f(Sa[nt][0] - m0);
            float p01 = exp2f(Sa[nt][1] - m0);
            float p10 = exp2f(Sa[nt][2] - m1);
            float p11 = exp2f(Sa[nt][3] - m1);
            s0 += p00 + p01; s1 += p10 + p11;
            int col = nt * 8 + 2 * (lane & 3);
            Ps[pr * AQS + col]           = __float_as_uint(p00);
            Ps[pr * AQS + col + 1]       = __float_as_uint(p01);
            Ps[(pr + 8) * AQS + col]     = __float_as_uint(p10);
            Ps[(pr + 8) * AQS + col + 1] = __float_as_uint(p11);
        }
        #pragma unroll
        for (int o = 1; o <= 2; o <<= 1) {
            s0 += __shfl_xor_sync(0xffffffffu, s0, o);
            s1 += __shfl_xor_sync(0xffffffffu, s1, o);
        }
        l0 = l0 * corr0 + s0;
        l1 = l1 * corr1 + s1;
        #pragma unroll
        for (int nt = 0; nt < 8; nt++) {
            Oa[nt][0] *= corr0; Oa[nt][1] *= corr0;
            Oa[nt][2] *= corr1; Oa[nt][3] *= corr1;
        }
        __syncwarp();

        // V[kt] must be resident (oldest outstanding group), K(kt+1) may fly
        if (kt + 1 < NT) { CP_WAIT1(); } else { CP_WAIT0(); }
        __syncthreads();

        // ---- O += P @ V ----
        #pragma unroll
        for (int kk = 0; kk < 64; kk += 8) {
            uint32_t af[4];
            int r = wid * 16 + (lane >> 2);
            int c = kk + (lane & 3);
            af[0] = Ps[r * AQS + c];
            af[1] = Ps[(r + 8) * AQS + c];
            af[2] = Ps[r * AQS + c + 4];
            af[3] = Ps[(r + 8) * AQS + c + 4];
            #pragma unroll
            for (int nt = 0; nt < 8; nt++) {
                uint32_t bf[2];
                bf[0] = Vs[(kk + (lane & 3)) * AVS + nt * 8 + (lane >> 2)];
                bf[1] = Vs[(kk + (lane & 3) + 4) * AVS + nt * 8 + (lane >> 2)];
                mma_tf32(Oa[nt], af, bf);
            }
        }
        __syncthreads();                     // all warps done with V[kt]
        if (kt + 1 < NT) {
            copy_v(kt + 1); CP_COMMIT();
            CP_WAIT1();                      // K(kt+1) ready; V(kt+1) in flight
            __syncthreads();
        }
    }

    float inv0 = 1.f / l0, inv1 = 1.f / l1;
    size_t r = qbase + wid * 16 + (lane >> 2);
    #pragma unroll
    for (int nt = 0; nt < 8; nt++) {
        int col = h * 64 + nt * 8 + 2 * (lane & 3);
        *(float2*)&g_attn[r * DIM + col] =
            make_float2(Oa[nt][0] * inv0, Oa[nt][1] * inv0);
        *(float2*)&g_attn[(r + 8) * DIM + col] =
            make_float2(Oa[nt][2] * inv1, Oa[nt][3] * inv1);
    }
}

// ---------------- residual + layernorm ---------------------------------------
__global__ __launch_bounds__(256) void k_ln(const float* __restrict__ gamma,
                                            const float* __restrict__ beta,
                                            float* __restrict__ out)
{
    __shared__ float ws[8], wss[8];
    const int row = blockIdx.x;
    const int tid = threadIdx.x;

    const float4* p4 = (const float4*)(g_proj + (size_t)row * DIM);
    const float4* x4 = (const float4*)(g_xpe  + (size_t)row * DIM);
    float4 a = p4[tid];
    float4 b = x4[tid];
    float4 hv = make_float4(a.x + b.x, a.y + b.y, a.z + b.z, a.w + b.w);

    float s  = hv.x + hv.y + hv.z + hv.w;
    float ss = hv.x * hv.x + hv.y * hv.y + hv.z * hv.z + hv.w * hv.w;
    #pragma unroll
    for (int o = 16; o; o >>= 1) {
        s  += __shfl_xor_sync(0xffffffffu, s,  o);
        ss += __shfl_xor_sync(0xffffffffu, ss, o);
    }
    int w = tid >> 5;
    if ((tid & 31) == 0) { ws[w] = s; wss[w] = ss; }
    __syncthreads();

    float ts = 0.f, tss = 0.f;
    #pragma unroll
    for (int i = 0; i < 8; i++) { ts += ws[i]; tss += wss[i]; }
    float mean = ts * (1.f / 1024.f);
    float var  = tss * (1.f / 1024.f) - mean * mean;
    float rstd = rsqrtf(var + 1e-5f);

    float4 g  = ((const float4*)gamma)[tid];
    float4 be = ((const float4*)beta)[tid];
    float4 o;
    o.x = (hv.x - mean) * rstd * g.x + be.x;
    o.y = (hv.y - mean) * rstd * g.y + be.y;
    o.z = (hv.z - mean) * rstd * g.z + be.z;
    o.w = (hv.w - mean) * rstd * g.w + be.w;
    ((float4*)out)[(size_t)row * 256 + tid] = o;
}

// ---------------- launch ------------------------------------------------------
extern "C" void kernel_launch(void* const* d_in, const int* in_sizes, int n_in,
                              void* d_out, int out_size)
{
    const float* x     = (const float*)d_in[0];
    const float* wq    = (const float*)d_in[1];
    const float* bq    = (const float*)d_in[2];
    const float* wk    = (const float*)d_in[3];
    const float* bk    = (const float*)d_in[4];
    const float* wv    = (const float*)d_in[5];
    const float* bv    = (const float*)d_in[6];
    const float* wo    = (const float*)d_in[7];
    const float* bo    = (const float*)d_in[8];
    const float* gamma = (const float*)d_in[9];
    const float* beta  = (const float*)d_in[10];
    const float* pe    = (const float*)d_in[11];
    float* out = (float*)d_out;

    void *pxpe, *pq, *pk, *pv, *pattn, *pproj, *pwT;
    cudaGetSymbolAddress(&pxpe,  g_xpe);
    cudaGetSymbolAddress(&pq,    g_q);
    cudaGetSymbolAddress(&pk,    g_k);
    cudaGetSymbolAddress(&pv,    g_v);
    cudaGetSymbolAddress(&pattn, g_attn);
    cudaGetSymbolAddress(&pproj, g_proj);
    cudaGetSymbolAddress(&pwT,   g_wT);
    float* wT = (float*)pwT;

    cudaFuncSetAttribute(k_gemm_mma, cudaFuncAttributeMaxDynamicSharedMemorySize, GSMEM);
    cudaFuncSetAttribute(k_attn_mma, cudaFuncAttributeMaxDynamicSharedMemorySize, ASMEM);

    k_addpe<<<(NTOK * DIM / 4) / 256, 256>>>(x, pe);

    dim3 tgrid(DIM / 32, DIM / 32, 4);
    k_transpose4<<<tgrid, 256>>>(wq, wk, wv, wo);

    // fused QKV projections: grid.x = 3*8
    dim3 qkvgrid(24, NTOK / 128);
    k_gemm_mma<<<qkvgrid, 256, GSMEM>>>(
        (const float*)pxpe,
        wT + 0 * DIM * DIM, wT + 1 * DIM * DIM, wT + 2 * DIM * DIM,
        bq, bk, bv,
        (float*)pq, (float*)pk, (float*)pv);

    dim3 agrid(SEQ / 128, NH, BATCH);            // (16, 16, 4)
    k_attn_mma<<<agrid, 256, ASMEM>>>();

    // output projection: single selection (which=0)
    dim3 ogrid(8, NTOK / 128);
    k_gemm_mma<<<ogrid, 256, GSMEM>>>(
        (const float*)pattn,
        wT + 3 * DIM * DIM, wT + 3 * DIM * DIM, wT + 3 * DIM * DIM,
        bo, bo, bo,
        (float*)pproj, (float*)pproj, (float*)pproj);

    k_ln<<<NTOK, 256>>>(gamma, beta, out);
}

// round 7
// speedup vs baseline: 1.1614x; 1.1614x over previous
#include <cuda_runtime.h>
#include <cstdint>

#define SEQ   2048
#define BATCH 4
#define NTOK  (SEQ * BATCH)      // 8192
#define DIM   1024
#define NH    16
#define HD    64

// ---------------- scratch (device globals per allocation rules) -------------
__device__ float g_xpe [NTOK * DIM];
__device__ float g_q   [NTOK * DIM];
__device__ float g_k   [NTOK * DIM];
__device__ float g_v   [NTOK * DIM];
__device__ float g_attn[NTOK * DIM];
__device__ float g_proj[NTOK * DIM];
__device__ float g_wT  [4][DIM * DIM];   // transposed weights [N,K]

// ---------------- helpers -----------------------------------------------------
__device__ __forceinline__ uint32_t smem_u32(const void* p) {
    uint32_t a;
    asm("{ .reg .u64 t; cvta.to.shared.u64 t, %1; cvt.u32.u64 %0, t; }" : "=r"(a) : "l"(p));
    return a;
}
__device__ __forceinline__ void cp16(uint32_t dst, const void* src) {
    asm volatile("cp.async.cg.shared.global [%0], [%1], 16;" :: "r"(dst), "l"(src));
}
#define CP_COMMIT() asm volatile("cp.async.commit_group;" ::: "memory")
#define CP_WAIT0()  asm volatile("cp.async.wait_group 0;" ::: "memory")

// raw fp32 bits as tf32 operands (HW truncates low mantissa bits)
__device__ __forceinline__ void mma_tf32(float* d, const uint32_t* a, const uint32_t* b) {
    asm volatile(
        "mma.sync.aligned.m16n8k8.row.col.f32.tf32.tf32.f32 "
        "{%0,%1,%2,%3}, {%4,%5,%6,%7}, {%8,%9}, {%0,%1,%2,%3};\n"
        : "+f"(d[0]), "+f"(d[1]), "+f"(d[2]), "+f"(d[3])
        : "r"(a[0]), "r"(a[1]), "r"(a[2]), "r"(a[3]), "r"(b[0]), "r"(b[1]));
}

// ---------------- x + pe ----------------------------------------------------
__global__ void k_addpe(const float* __restrict__ x, const float* __restrict__ pe) {
    int idx = blockIdx.x * 256 + threadIdx.x;
    const float4* x4  = (const float4*)x;
    const float4* pe4 = (const float4*)pe;
    float4*       o4  = (float4*)g_xpe;
    int row = idx >> 8;
    int c   = idx & 255;
    int s   = row & (SEQ - 1);
    float4 a = x4[idx];
    float4 b = pe4[s * 256 + c];
    a.x += b.x; a.y += b.y; a.z += b.z; a.w += b.w;
    o4[idx] = a;
}

// ---------------- fused weight transpose (4 weights via blockIdx.z) ----------
__global__ __launch_bounds__(256) void k_transpose4(
    const float* __restrict__ w0, const float* __restrict__ w1,
    const float* __restrict__ w2, const float* __restrict__ w3)
{
    __shared__ float t[32][33];
    const float* in;
    switch (blockIdx.z) {
        case 0: in = w0; break;
        case 1: in = w1; break;
        case 2: in = w2; break;
        default: in = w3; break;
    }
    float* out = g_wT[blockIdx.z];
    int n0 = blockIdx.x * 32, k0 = blockIdx.y * 32;
    int tx = threadIdx.x & 31, ty = threadIdx.x >> 5;
    #pragma unroll
    for (int i = ty; i < 32; i += 8)
        t[i][tx] = in[(size_t)(k0 + i) * DIM + n0 + tx];
    __syncthreads();
    #pragma unroll
    for (int i = ty; i < 32; i += 8)
        out[(size_t)(n0 + i) * DIM + k0 + tx] = t[tx][i];
}

// ---------------- tf32 mma GEMM: C[M,N] = A[M,K] @ Bt[N,K]^T + bias ---------
// 128x128 CTA tile, BK=32, 8 warps (4x2), warp tile 32x64, cp.async dbl-buffer
#define GPAD  36
#define GTILE (128 * GPAD)
#define GSMEM (4 * GTILE * 4)              // 73728 bytes
#define NC    (DIM / 32)

__global__ __launch_bounds__(256) void k_gemm_mma(
    const float* __restrict__ A, const float* __restrict__ Bt,
    const float* __restrict__ bias, float* __restrict__ C)
{
    extern __shared__ uint32_t sm[];
    const uint32_t smb = smem_u32(sm);
    const int tid  = threadIdx.x;
    const int lane = tid & 31;
    const int wid  = tid >> 5;
    const int wr   = wid & 3;
    const int wc   = wid >> 2;
    const int rowBase = blockIdx.y * 128;
    const int colBase = blockIdx.x * 128;

    const float* Ab = A  + (size_t)rowBase * DIM;
    const float* Bb = Bt + (size_t)colBase * DIM;

    float acc[2][8][4];
    #pragma unroll
    for (int mt = 0; mt < 2; mt++)
        #pragma unroll
        for (int nt = 0; nt < 8; nt++)
            #pragma unroll
            for (int j = 0; j < 4; j++) acc[mt][nt][j] = 0.f;

    auto copy_tile = [&](int buf, int chunk) {
        uint32_t as_ = smb + buf * 2 * GTILE * 4;
        uint32_t bs_ = as_ + GTILE * 4;
        #pragma unroll
        for (int i = 0; i < 4; i++) {
            int idx = i * 256 + tid;
            int r = idx >> 3, c4 = idx & 7;
            uint32_t off = (r * GPAD + c4 * 4) * 4;
            cp16(as_ + off, Ab + (size_t)r * DIM + chunk * 32 + c4 * 4);
            cp16(bs_ + off, Bb + (size_t)r * DIM + chunk * 32 + c4 * 4);
        }
    };
    auto compute = [&](int buf) {
        const uint32_t* as_ = sm + buf * 2 * GTILE;
        const uint32_t* bs_ = as_ + GTILE;
        #pragma unroll
        for (int kk = 0; kk < 32; kk += 8) {
            uint32_t af[2][4];
            #pragma unroll
            for (int mt = 0; mt < 2; mt++) {
                int r = wr * 32 + mt * 16 + (lane >> 2);
                int c = kk + (lane & 3);
                af[mt][0] = as_[r * GPAD + c];
                af[mt][1] = as_[(r + 8) * GPAD + c];
                af[mt][2] = as_[r * GPAD + c + 4];
                af[mt][3] = as_[(r + 8) * GPAD + c + 4];
            }
            #pragma unroll
            for (int nt = 0; nt < 8; nt++) {
                int n = wc * 64 + nt * 8 + (lane >> 2);
                uint32_t bf[2];
                bf[0] = bs_[n * GPAD + kk + (lane & 3)];
                bf[1] = bs_[n * GPAD + kk + (lane & 3) + 4];
                mma_tf32(acc[0][nt], af[0], bf);
                mma_tf32(acc[1][nt], af[1], bf);
            }
        }
    };

    copy_tile(0, 0); CP_COMMIT();
    CP_WAIT0(); __syncthreads();
    for (int c = 0; c < NC; c++) {
        int b = c & 1;
        if (c + 1 < NC) { copy_tile(b ^ 1, c + 1); CP_COMMIT(); }
        compute(b);
        CP_WAIT0(); __syncthreads();
    }

    #pragma unroll
    for (int mt = 0; mt < 2; mt++) {
        int r = rowBase + wr * 32 + mt * 16 + (lane >> 2);
        #pragma unroll
        for (int nt = 0; nt < 8; nt++) {
            int col = colBase + wc * 64 + nt * 8 + 2 * (lane & 3);
            float2 b2 = *(const float2*)&bias[col];
            float2 o0 = make_float2(acc[mt][nt][0] + b2.x, acc[mt][nt][1] + b2.y);
            float2 o1 = make_float2(acc[mt][nt][2] + b2.x, acc[mt][nt][3] + b2.y);
            *(float2*)&C[(size_t)r * DIM + col]       = o0;
            *(float2*)&C[(size_t)(r + 8) * DIM + col] = o1;
        }
    }
}

// ---------------- flash attention via mma ------------------------------------
// 256 threads / 8 warps, 128 queries per CTA; warp owns 16 q-rows.
// K+V double-buffered via cp.async; P stays in registers (quad-shfl fragment
// conversion, no smem round trip). One __syncthreads per kt tile.
#define AQS 68
#define AVS 72
#define QWORDS (128 * AQS)                     // 8704
#define KVST   (64 * AQS + 64 * AVS)           // 8960 words per stage
#define OFF_K(b) (QWORDS + (b) * KVST)
#define OFF_V(b) (QWORDS + (b) * KVST + 64 * AQS)
#define ASMEM  ((QWORDS + 2 * KVST) * 4)       // 106496 bytes
#define NT   (SEQ / 64)
#define SCL  0.18033688011112042f              // 0.125 * log2(e)

__global__ __launch_bounds__(256) void k_attn_mma()
{
    extern __shared__ uint32_t sm[];
    const uint32_t smb = smem_u32(sm);
    uint32_t* Qs = sm;

    const int tid  = threadIdx.x;
    const int lane = tid & 31;
    const int wid  = tid >> 5;
    const int j    = lane & 3;
    const int srcA = (lane & ~3) | (j >> 1);
    const int srcB = srcA + 2;
    const int qt = blockIdx.x, h = blockIdx.y, b = blockIdx.z;
    const size_t qbase  = (size_t)(b * SEQ + qt * 128);
    const size_t kvbase = (size_t)(b * SEQ) * DIM + h * 64;

    auto copy_q = [&]() {
        #pragma unroll
        for (int i = 0; i < 8; i++) {
            int idx = i * 256 + tid;
            int r = idx >> 4, c4 = idx & 15;
            cp16(smb + (r * AQS + c4 * 4) * 4,
                 g_q + (qbase + r) * DIM + h * 64 + c4 * 4);
        }
    };
    auto copy_kv = [&](int buf, int kt) {
        uint32_t kb = smb + OFF_K(buf) * 4;
        uint32_t vb = smb + OFF_V(buf) * 4;
        #pragma unroll
        for (int i = 0; i < 4; i++) {
            int idx = i * 256 + tid;
            int r = idx >> 4, c4 = idx & 15;
            size_t g = kvbase + (size_t)(kt * 64 + r) * DIM + c4 * 4;
            cp16(kb + (r * AQS + c4 * 4) * 4, g_k + g);
            cp16(vb + (r * AVS + c4 * 4) * 4, g_v + g);
        }
    };

    float Oa[8][4];
    #pragma unroll
    for (int nt = 0; nt < 8; nt++)
        #pragma unroll
        for (int jj = 0; jj < 4; jj++) Oa[nt][jj] = 0.f;
    float m0 = -1e30f, m1 = -1e30f, l0 = 0.f, l1 = 0.f;   // log2 domain

    copy_q(); copy_kv(0, 0); CP_COMMIT();
    CP_WAIT0(); __syncthreads();

    for (int kt = 0; kt < NT; kt++) {
        int bu = kt & 1;
        if (kt + 1 < NT) { copy_kv(bu ^ 1, kt + 1); CP_COMMIT(); }

        const uint32_t* Ks = sm + OFF_K(bu);
        const uint32_t* Vs = sm + OFF_V(bu);

        // ---- S = Q @ K^T ----
        float Sa[8][4];
        #pragma unroll
        for (int nt = 0; nt < 8; nt++)
            #pragma unroll
            for (int jj = 0; jj < 4; jj++) Sa[nt][jj] = 0.f;
        #pragma unroll
        for (int kk = 0; kk < 64; kk += 8) {
            uint32_t af[4];
            int r = wid * 16 + (lane >> 2);
            int c = kk + j;
            af[0] = Qs[r * AQS + c];
            af[1] = Qs[(r + 8) * AQS + c];
            af[2] = Qs[r * AQS + c + 4];
            af[3] = Qs[(r + 8) * AQS + c + 4];
            #pragma unroll
            for (int nt = 0; nt < 8; nt++) {
                int n = nt * 8 + (lane >> 2);
                uint32_t bf[2];
                bf[0] = Ks[n * AQS + kk + j];
                bf[1] = Ks[n * AQS + kk + j + 4];
                mma_tf32(Sa[nt], af, bf);
            }
        }

        // ---- online softmax (exp2 domain); P left in Sa registers ----
        #pragma unroll
        for (int nt = 0; nt < 8; nt++)
            #pragma unroll
            for (int jj = 0; jj < 4; jj++) Sa[nt][jj] *= SCL;

        float mx0 = m0, mx1 = m1;
        #pragma unroll
        for (int nt = 0; nt < 8; nt++) {
            mx0 = fmaxf(mx0, fmaxf(Sa[nt][0], Sa[nt][1]));
            mx1 = fmaxf(mx1, fmaxf(Sa[nt][2], Sa[nt][3]));
        }
        #pragma unroll
        for (int o = 1; o <= 2; o <<= 1) {
            mx0 = fmaxf(mx0, __shfl_xor_sync(0xffffffffu, mx0, o));
            mx1 = fmaxf(mx1, __shfl_xor_sync(0xffffffffu, mx1, o));
        }
        float corr0 = exp2f(m0 - mx0);
        float corr1 = exp2f(m1 - mx1);
        m0 = mx0; m1 = mx1;

        float s0 = 0.f, s1 = 0.f;
        #pragma unroll
        for (int nt = 0; nt < 8; nt++) {
            Sa[nt][0] = exp2f(Sa[nt][0] - m0);
            Sa[nt][1] = exp2f(Sa[nt][1] - m0);
            Sa[nt][2] = exp2f(Sa[nt][2] - m1);
            Sa[nt][3] = exp2f(Sa[nt][3] - m1);
            s0 += Sa[nt][0] + Sa[nt][1];
            s1 += Sa[nt][2] + Sa[nt][3];
        }
        #pragma unroll
        for (int o = 1; o <= 2; o <<= 1) {
            s0 += __shfl_xor_sync(0xffffffffu, s0, o);
            s1 += __shfl_xor_sync(0xffffffffu, s1, o);
        }
        l0 = l0 * corr0 + s0;
        l1 = l1 * corr1 + s1;
        #pragma unroll
        for (int nt = 0; nt < 8; nt++) {
            Oa[nt][0] *= corr0; Oa[nt][1] *= corr0;
            Oa[nt][2] *= corr1; Oa[nt][3] *= corr1;
        }

        // ---- O += P @ V  (A-frag built from Sa via quad shfl) ----
        #pragma unroll
        for (int kk = 0; kk < 8; kk++) {
            float u0 = __shfl_sync(0xffffffffu, Sa[kk][0], srcA);
            float u1 = __shfl_sync(0xffffffffu, Sa[kk][1], srcA);
            float w0 = __shfl_sync(0xffffffffu, Sa[kk][2], srcA);
            float w1 = __shfl_sync(0xffffffffu, Sa[kk][3], srcA);
            float v0 = __shfl_sync(0xffffffffu, Sa[kk][0], srcB);
            float v1 = __shfl_sync(0xffffffffu, Sa[kk][1], srcB);
            float x0 = __shfl_sync(0xffffffffu, Sa[kk][2], srcB);
            float x1 = __shfl_sync(0xffffffffu, Sa[kk][3], srcB);
            bool odd = (j & 1) != 0;
            uint32_t af[4];
            af[0] = __float_as_uint(odd ? u1 : u0);
            af[1] = __float_as_uint(odd ? w1 : w0);
            af[2] = __float_as_uint(odd ? v1 : v0);
            af[3] = __float_as_uint(odd ? x1 : x0);
            #pragma unroll
            for (int nt = 0; nt < 8; nt++) {
                uint32_t bf[2];
                bf[0] = Vs[(kk * 8 + j) * AVS + nt * 8 + (lane >> 2)];
                bf[1] = Vs[(kk * 8 + j + 4) * AVS + nt * 8 + (lane >> 2)];
                mma_tf32(Oa[nt], af, bf);
            }
        }

        CP_WAIT0(); __syncthreads();
    }

    float inv0 = 1.f / l0, inv1 = 1.f / l1;
    size_t r = qbase + wid * 16 + (lane >> 2);
    #pragma unroll
    for (int nt = 0; nt < 8; nt++) {
        int col = h * 64 + nt * 8 + 2 * j;
        *(float2*)&g_attn[r * DIM + col] =
            make_float2(Oa[nt][0] * inv0, Oa[nt][1] * inv0);
        *(float2*)&g_attn[(r + 8) * DIM + col] =
            make_float2(Oa[nt][2] * inv1, Oa[nt][3] * inv1);
    }
}

// ---------------- residual + layernorm ---------------------------------------
__global__ __launch_bounds__(256) void k_ln(const float* __restrict__ gamma,
                                            const float* __restrict__ beta,
                                            float* __restrict__ out)
{
    __shared__ float ws[8], wss[8];
    const int row = blockIdx.x;
    const int tid = threadIdx.x;

    const float4* p4 = (const float4*)(g_proj + (size_t)row * DIM);
    const float4* x4 = (const float4*)(g_xpe  + (size_t)row * DIM);
    float4 a = p4[tid];
    float4 b = x4[tid];
    float4 hv = make_float4(a.x + b.x, a.y + b.y, a.z + b.z, a.w + b.w);

    float s  = hv.x + hv.y + hv.z + hv.w;
    float ss = hv.x * hv.x + hv.y * hv.y + hv.z * hv.z + hv.w * hv.w;
    #pragma unroll
    for (int o = 16; o; o >>= 1) {
        s  += __shfl_xor_sync(0xffffffffu, s,  o);
        ss += __shfl_xor_sync(0xffffffffu, ss, o);
    }
    int w = tid >> 5;
    if ((tid & 31) == 0) { ws[w] = s; wss[w] = ss; }
    __syncthreads();

    float ts = 0.f, tss = 0.f;
    #pragma unroll
    for (int i = 0; i < 8; i++) { ts += ws[i]; tss += wss[i]; }
    float mean = ts * (1.f / 1024.f);
    float var  = tss * (1.f / 1024.f) - mean * mean;
    float rstd = rsqrtf(var + 1e-5f);

    float4 g  = ((const float4*)gamma)[tid];
    float4 be = ((const float4*)beta)[tid];
    float4 o;
    o.x = (hv.x - mean) * rstd * g.x + be.x;
    o.y = (hv.y - mean) * rstd * g.y + be.y;
    o.z = (hv.z - mean) * rstd * g.z + be.z;
    o.w = (hv.w - mean) * rstd * g.w + be.w;
    ((float4*)out)[(size_t)row * 256 + tid] = o;
}

// ---------------- launch ------------------------------------------------------
extern "C" void kernel_launch(void* const* d_in, const int* in_sizes, int n_in,
                              void* d_out, int out_size)
{
    const float* x     = (const float*)d_in[0];
    const float* wq    = (const float*)d_in[1];
    const float* bq    = (const float*)d_in[2];
    const float* wk    = (const float*)d_in[3];
    const float* bk    = (const float*)d_in[4];
    const float* wv    = (const float*)d_in[5];
    const float* bv    = (const float*)d_in[6];
    const float* wo    = (const float*)d_in[7];
    const float* bo    = (const float*)d_in[8];
    const float* gamma = (const float*)d_in[9];
    const float* beta  = (const float*)d_in[10];
    const float* pe    = (const float*)d_in[11];
    float* out = (float*)d_out;

    void *pxpe, *pq, *pk, *pv, *pattn, *pproj, *pwT;
    cudaGetSymbolAddress(&pxpe,  g_xpe);
    cudaGetSymbolAddress(&pq,    g_q);
    cudaGetSymbolAddress(&pk,    g_k);
    cudaGetSymbolAddress(&pv,    g_v);
    cudaGetSymbolAddress(&pattn, g_attn);
    cudaGetSymbolAddress(&pproj, g_proj);
    cudaGetSymbolAddress(&pwT,   g_wT);
    float* wT = (float*)pwT;

    cudaFuncSetAttribute(k_gemm_mma, cudaFuncAttributeMaxDynamicSharedMemorySize, GSMEM);
    cudaFuncSetAttribute(k_attn_mma, cudaFuncAttributeMaxDynamicSharedMemorySize, ASMEM);

    k_addpe<<<(NTOK * DIM / 4) / 256, 256>>>(x, pe);

    dim3 tgrid(DIM / 32, DIM / 32, 4);
    k_transpose4<<<tgrid, 256>>>(wq, wk, wv, wo);

    dim3 ggrid(DIM / 128, NTOK / 128);           // (8, 64)
    k_gemm_mma<<<ggrid, 256, GSMEM>>>((const float*)pxpe, wT + 0 * DIM * DIM, bq, (float*)pq);
    k_gemm_mma<<<ggrid, 256, GSMEM>>>((const float*)pxpe, wT + 1 * DIM * DIM, bk, (float*)pk);
    k_gemm_mma<<<ggrid, 256, GSMEM>>>((const float*)pxpe, wT + 2 * DIM * DIM, bv, (float*)pv);

    dim3 agrid(SEQ / 128, NH, BATCH);            // (16, 16, 4)
    k_attn_mma<<<agrid, 256, ASMEM>>>();

    k_gemm_mma<<<ggrid, 256, GSMEM>>>((const float*)pattn, wT + 3 * DIM * DIM, bo, (float*)pproj);

    k_ln<<<NTOK, 256>>>(gamma, beta, out);
}

// round 8
// speedup vs baseline: 1.9719x; 1.6979x over previous
#include <cuda_runtime.h>
#include <cuda_fp16.h>
#include <cstdint>

#define SEQ   2048
#define BATCH 4
#define NTOK  (SEQ * BATCH)      // 8192
#define DIM   1024
#define NH    16
#define HD    64

// ---------------- scratch (device globals per allocation rules) -------------
__device__ float  g_xpe [NTOK * DIM];     // fp32 residual for LN
__device__ float  g_proj[NTOK * DIM];     // fp32 O-projection for LN
__device__ __half g_xh  [NTOK * DIM];     // half x+pe (GEMM A)
__device__ __half g_qh  [NTOK * DIM];
__device__ __half g_kh  [NTOK * DIM];
__device__ __half g_vh  [NTOK * DIM];
__device__ __half g_ah  [NTOK * DIM];     // attention output (half)
__device__ __half g_wTh [4][DIM * DIM];   // transposed weights [N][K], half

// ---------------- helpers -----------------------------------------------------
__device__ __forceinline__ uint32_t smem_u32(const void* p) {
    uint32_t a;
    asm("{ .reg .u64 t; cvta.to.shared.u64 t, %1; cvt.u32.u64 %0, t; }" : "=r"(a) : "l"(p));
    return a;
}
__device__ __forceinline__ void cp16(uint32_t dst, const void* src) {
    asm volatile("cp.async.cg.shared.global [%0], [%1], 16;" :: "r"(dst), "l"(src));
}
#define CP_COMMIT() asm volatile("cp.async.commit_group;" ::: "memory")
#define CP_WAIT0()  asm volatile("cp.async.wait_group 0;" ::: "memory")

__device__ __forceinline__ void mma_f16(float* d, const uint32_t* a, const uint32_t* b) {
    asm volatile(
        "mma.sync.aligned.m16n8k16.row.col.f32.f16.f16.f32 "
        "{%0,%1,%2,%3}, {%4,%5,%6,%7}, {%8,%9}, {%0,%1,%2,%3};\n"
        : "+f"(d[0]), "+f"(d[1]), "+f"(d[2]), "+f"(d[3])
        : "r"(a[0]), "r"(a[1]), "r"(a[2]), "r"(a[3]), "r"(b[0]), "r"(b[1]));
}
__device__ __forceinline__ uint32_t packh(__half x, __half y) {
    __half2 t = __halves2half2(x, y);
    return *(uint32_t*)&t;
}
__device__ __forceinline__ uint32_t packf(float x, float y) {
    __half2 t = __floats2half2_rn(x, y);
    return *(uint32_t*)&t;
}

// ---------------- x + pe (fp32 out + half out) -------------------------------
__global__ void k_addpe(const float* __restrict__ x, const float* __restrict__ pe) {
    int idx = blockIdx.x * 256 + threadIdx.x;        // float4 index
    const float4* x4  = (const float4*)x;
    const float4* pe4 = (const float4*)pe;
    float4*       o4  = (float4*)g_xpe;
    int row = idx >> 8;
    int c   = idx & 255;
    int s   = row & (SEQ - 1);
    float4 a = x4[idx];
    float4 b = pe4[s * 256 + c];
    a.x += b.x; a.y += b.y; a.z += b.z; a.w += b.w;
    o4[idx] = a;
    uint2 hp;
    hp.x = packf(a.x, a.y);
    hp.y = packf(a.z, a.w);
    *(uint2*)&g_xh[(size_t)idx * 4] = hp;
}

// ---------------- fused weight transpose -> half ------------------------------
__global__ __launch_bounds__(256) void k_transpose4(
    const float* __restrict__ w0, const float* __restrict__ w1,
    const float* __restrict__ w2, const float* __restrict__ w3)
{
    __shared__ float t[32][33];
    const float* in;
    switch (blockIdx.z) {
        case 0: in = w0; break;
        case 1: in = w1; break;
        case 2: in = w2; break;
        default: in = w3; break;
    }
    __half* out = g_wTh[blockIdx.z];
    int n0 = blockIdx.x * 32, k0 = blockIdx.y * 32;
    int tx = threadIdx.x & 31, ty = threadIdx.x >> 5;
    #pragma unroll
    for (int i = ty; i < 32; i += 8)
        t[i][tx] = in[(size_t)(k0 + i) * DIM + n0 + tx];
    __syncthreads();
    #pragma unroll
    for (int i = ty; i < 32; i += 8)
        out[(size_t)(n0 + i) * DIM + k0 + tx] = __float2half(t[tx][i]);
}

// ---------------- fp16 mma GEMM: C[M,N] = A[M,K] @ Bt[N,K]^T + bias ----------
// 128x128 CTA tile, BK=64 halves, 8 warps (4x2), warp tile 32x64, dbl-buffer.
#define GPADH 72
#define TILEH (128 * GPADH)                 // halves per tile
#define GSMEM (4 * TILEH * 2)               // 73728 bytes
#define NCH   (DIM / 64)                    // 16 stages

template <typename OutT>
__global__ __launch_bounds__(256) void k_gemm_h(
    const __half* __restrict__ A, const __half* __restrict__ Bt,
    const float* __restrict__ bias, OutT* __restrict__ C)
{
    extern __shared__ __half smh[];
    const uint32_t smb = smem_u32(smh);
    const int tid  = threadIdx.x;
    const int lane = tid & 31;
    const int wid  = tid >> 5;
    const int wr   = wid & 3;
    const int wc   = wid >> 2;
    const int j    = lane & 3;
    const int rowBase = blockIdx.y * 128;
    const int colBase = blockIdx.x * 128;

    const __half* Ab = A  + (size_t)rowBase * DIM;
    const __half* Bb = Bt + (size_t)colBase * DIM;

    float acc[2][8][4];
    #pragma unroll
    for (int mt = 0; mt < 2; mt++)
        #pragma unroll
        for (int nt = 0; nt < 8; nt++)
            #pragma unroll
            for (int q = 0; q < 4; q++) acc[mt][nt][q] = 0.f;

    auto copy_tile = [&](int buf, int chunk) {
        uint32_t as_ = smb + buf * 2 * TILEH * 2;
        uint32_t bs_ = as_ + TILEH * 2;
        #pragma unroll
        for (int i = 0; i < 4; i++) {
            int idx = i * 256 + tid;        // 0..1023
            int r = idx >> 3, c8 = idx & 7; // row, 8-half chunk
            uint32_t off = (r * GPADH + c8 * 8) * 2;
            cp16(as_ + off, Ab + (size_t)r * DIM + chunk * 64 + c8 * 8);
            cp16(bs_ + off, Bb + (size_t)r * DIM + chunk * 64 + c8 * 8);
        }
    };
    auto compute = [&](int buf) {
        const __half* as_ = smh + buf * 2 * TILEH;
        const __half* bs_ = as_ + TILEH;
        #pragma unroll
        for (int kk = 0; kk < 64; kk += 16) {
            uint32_t af[2][4];
            #pragma unroll
            for (int mt = 0; mt < 2; mt++) {
                int r = wr * 32 + mt * 16 + (lane >> 2);
                int c = kk + 2 * j;
                af[mt][0] = *(const uint32_t*)&as_[r * GPADH + c];
                af[mt][1] = *(const uint32_t*)&as_[(r + 8) * GPADH + c];
                af[mt][2] = *(const uint32_t*)&as_[r * GPADH + c + 8];
                af[mt][3] = *(const uint32_t*)&as_[(r + 8) * GPADH + c + 8];
            }
            #pragma unroll
            for (int nt = 0; nt < 8; nt++) {
                int n = wc * 64 + nt * 8 + (lane >> 2);
                uint32_t bf[2];
                bf[0] = *(const uint32_t*)&bs_[n * GPADH + kk + 2 * j];
                bf[1] = *(const uint32_t*)&bs_[n * GPADH + kk + 2 * j + 8];
                mma_f16(acc[0][nt], af[0], bf);
                mma_f16(acc[1][nt], af[1], bf);
            }
        }
    };

    copy_tile(0, 0); CP_COMMIT();
    CP_WAIT0(); __syncthreads();
    for (int c = 0; c < NCH; c++) {
        int b = c & 1;
        if (c + 1 < NCH) { copy_tile(b ^ 1, c + 1); CP_COMMIT(); }
        compute(b);
        CP_WAIT0(); __syncthreads();
    }

    #pragma unroll
    for (int mt = 0; mt < 2; mt++) {
        int r = rowBase + wr * 32 + mt * 16 + (lane >> 2);
        #pragma unroll
        for (int nt = 0; nt < 8; nt++) {
            int col = colBase + wc * 64 + nt * 8 + 2 * j;
            float2 b2 = *(const float2*)&bias[col];
            float o00 = acc[mt][nt][0] + b2.x, o01 = acc[mt][nt][1] + b2.y;
            float o10 = acc[mt][nt][2] + b2.x, o11 = acc[mt][nt][3] + b2.y;
            if constexpr (sizeof(OutT) == 2) {
                *(uint32_t*)&C[(size_t)r * DIM + col]       = packf(o00, o01);
                *(uint32_t*)&C[(size_t)(r + 8) * DIM + col] = packf(o10, o11);
            } else {
                *(float2*)&C[(size_t)r * DIM + col]       = make_float2(o00, o01);
                *(float2*)&C[(size_t)(r + 8) * DIM + col] = make_float2(o10, o11);
            }
        }
    }
}

// ---------------- flash attention, fp16 mma ----------------------------------
// 256 threads / 8 warps, 128 queries per CTA; warp owns 16 q-rows.
// K+V double-buffered; P converted to fp16 A-frags by pure register packing.
#define AQSH 72
#define QH    (128 * AQSH)                 // 9216 halves
#define KVSTH (64 * AQSH * 2)              // K+V stage halves
#define OFFK(b) (QH + (b) * KVSTH)
#define OFFV(b) (QH + (b) * KVSTH + 64 * AQSH)
#define ASMEM ((QH + 2 * KVSTH) * 2)       // 55296 bytes
#define NT    (SEQ / 64)
#define SCL   0.18033688011112042f         // 0.125 * log2(e)

__global__ __launch_bounds__(256) void k_attn_h()
{
    extern __shared__ __half smh[];
    const uint32_t smb = smem_u32(smh);

    const int tid  = threadIdx.x;
    const int lane = tid & 31;
    const int wid  = tid >> 5;
    const int j    = lane & 3;
    const int qt = blockIdx.x, h = blockIdx.y, b = blockIdx.z;
    const size_t qbase  = (size_t)(b * SEQ + qt * 128);
    const size_t kvbase = (size_t)(b * SEQ) * DIM + h * 64;

    auto copy_q = [&]() {
        #pragma unroll
        for (int i = 0; i < 4; i++) {
            int idx = i * 256 + tid;        // 1024 = 128 rows x 8 chunks
            int r = idx >> 3, c8 = idx & 7;
            cp16(smb + (r * AQSH + c8 * 8) * 2,
                 g_qh + (qbase + r) * DIM + h * 64 + c8 * 8);
        }
    };
    auto copy_kv = [&](int buf, int kt) {
        uint32_t kb = smb + OFFK(buf) * 2;
        uint32_t vb = smb + OFFV(buf) * 2;
        #pragma unroll
        for (int i = 0; i < 2; i++) {
            int idx = i * 256 + tid;        // 512 = 64 rows x 8 chunks
            int r = idx >> 3, c8 = idx & 7;
            size_t g = kvbase + (size_t)(kt * 64 + r) * DIM + c8 * 8;
            cp16(kb + (r * AQSH + c8 * 8) * 2, g_kh + g);
            cp16(vb + (r * AQSH + c8 * 8) * 2, g_vh + g);
        }
    };

    float Oa[8][4];
    #pragma unroll
    for (int nt = 0; nt < 8; nt++)
        #pragma unroll
        for (int q = 0; q < 4; q++) Oa[nt][q] = 0.f;
    float m0 = -1e30f, m1 = -1e30f, l0 = 0.f, l1 = 0.f;  // log2 domain

    copy_q(); copy_kv(0, 0); CP_COMMIT();
    CP_WAIT0(); __syncthreads();

    for (int kt = 0; kt < NT; kt++) {
        int bu = kt & 1;
        if (kt + 1 < NT) { copy_kv(bu ^ 1, kt + 1); CP_COMMIT(); }

        const __half* Qs = smh;
        const __half* Ks = smh + OFFK(bu);
        const __half* Vs = smh + OFFV(bu);

        // ---- S = Q @ K^T ----
        float Sa[8][4];
        #pragma unroll
        for (int nt = 0; nt < 8; nt++)
            #pragma unroll
            for (int q = 0; q < 4; q++) Sa[nt][q] = 0.f;
        #pragma unroll
        for (int kk = 0; kk < 64; kk += 16) {
            uint32_t af[4];
            int r = wid * 16 + (lane >> 2);
            int c = kk + 2 * j;
            af[0] = *(const uint32_t*)&Qs[r * AQSH + c];
            af[1] = *(const uint32_t*)&Qs[(r + 8) * AQSH + c];
            af[2] = *(const uint32_t*)&Qs[r * AQSH + c + 8];
            af[3] = *(const uint32_t*)&Qs[(r + 8) * AQSH + c + 8];
            #pragma unroll
            for (int nt = 0; nt < 8; nt++) {
                int n = nt * 8 + (lane >> 2);
                uint32_t bf[2];
                bf[0] = *(const uint32_t*)&Ks[n * AQSH + c];
                bf[1] = *(const uint32_t*)&Ks[n * AQSH + c + 8];
                mma_f16(Sa[nt], af, bf);
            }
        }

        // ---- online softmax (exp2 domain) ----
        #pragma unroll
        for (int nt = 0; nt < 8; nt++)
            #pragma unroll
            for (int q = 0; q < 4; q++) Sa[nt][q] *= SCL;

        float mx0 = m0, mx1 = m1;
        #pragma unroll
        for (int nt = 0; nt < 8; nt++) {
            mx0 = fmaxf(mx0, fmaxf(Sa[nt][0], Sa[nt][1]));
            mx1 = fmaxf(mx1, fmaxf(Sa[nt][2], Sa[nt][3]));
        }
        #pragma unroll
        for (int o = 1; o <= 2; o <<= 1) {
            mx0 = fmaxf(mx0, __shfl_xor_sync(0xffffffffu, mx0, o));
            mx1 = fmaxf(mx1, __shfl_xor_sync(0xffffffffu, mx1, o));
        }
        float corr0 = exp2f(m0 - mx0);
        float corr1 = exp2f(m1 - mx1);
        m0 = mx0; m1 = mx1;

        float s0 = 0.f, s1 = 0.f;
        #pragma unroll
        for (int nt = 0; nt < 8; nt++) {
            Sa[nt][0] = exp2f(Sa[nt][0] - m0);
            Sa[nt][1] = exp2f(Sa[nt][1] - m0);
            Sa[nt][2] = exp2f(Sa[nt][2] - m1);
            Sa[nt][3] = exp2f(Sa[nt][3] - m1);
            s0 += Sa[nt][0] + Sa[nt][1];
            s1 += Sa[nt][2] + Sa[nt][3];
        }
        #pragma unroll
        for (int o = 1; o <= 2; o <<= 1) {
            s0 += __shfl_xor_sync(0xffffffffu, s0, o);
            s1 += __shfl_xor_sync(0xffffffffu, s1, o);
        }
        l0 = l0 * corr0 + s0;
        l1 = l1 * corr1 + s1;
        #pragma unroll
        for (int nt = 0; nt < 8; nt++) {
            Oa[nt][0] *= corr0; Oa[nt][1] *= corr0;
            Oa[nt][2] *= corr1; Oa[nt][3] *= corr1;
        }

        // ---- O += P @ V  (A-frags = local packs of Sa; B from V via LDS16) ----
        #pragma unroll
        for (int kk2 = 0; kk2 < 4; kk2++) {
            uint32_t af[4];
            af[0] = packf(Sa[2 * kk2][0],     Sa[2 * kk2][1]);
            af[1] = packf(Sa[2 * kk2][2],     Sa[2 * kk2][3]);
            af[2] = packf(Sa[2 * kk2 + 1][0], Sa[2 * kk2 + 1][1]);
            af[3] = packf(Sa[2 * kk2 + 1][2], Sa[2 * kk2 + 1][3]);
            int krow = kk2 * 16 + 2 * j;
            #pragma unroll
            for (int nt = 0; nt < 8; nt++) {
                int n = nt * 8 + (lane >> 2);
                uint32_t bf[2];
                bf[0] = packh(Vs[krow * AQSH + n],       Vs[(krow + 1) * AQSH + n]);
                bf[1] = packh(Vs[(krow + 8) * AQSH + n], Vs[(krow + 9) * AQSH + n]);
                mma_f16(Oa[nt], af, bf);
            }
        }

        CP_WAIT0(); __syncthreads();
    }

    float inv0 = 1.f / l0, inv1 = 1.f / l1;
    size_t r = qbase + wid * 16 + (lane >> 2);
    #pragma unroll
    for (int nt = 0; nt < 8; nt++) {
        int col = h * 64 + nt * 8 + 2 * j;
        *(uint32_t*)&g_ah[r * DIM + col] =
            packf(Oa[nt][0] * inv0, Oa[nt][1] * inv0);
        *(uint32_t*)&g_ah[(r + 8) * DIM + col] =
            packf(Oa[nt][2] * inv1, Oa[nt][3] * inv1);
    }
}

// ---------------- residual + layernorm ---------------------------------------
__global__ __launch_bounds__(256) void k_ln(const float* __restrict__ gamma,
                                            const float* __restrict__ beta,
                                            float* __restrict__ out)
{
    __shared__ float ws[8], wss[8];
    const int row = blockIdx.x;
    const int tid = threadIdx.x;

    const float4* p4 = (const float4*)(g_proj + (size_t)row * DIM);
    const float4* x4 = (const float4*)(g_xpe  + (size_t)row * DIM);
    float4 a = p4[tid];
    float4 b = x4[tid];
    float4 hv = make_float4(a.x + b.x, a.y + b.y, a.z + b.z, a.w + b.w);

    float s  = hv.x + hv.y + hv.z + hv.w;
    float ss = hv.x * hv.x + hv.y * hv.y + hv.z * hv.z + hv.w * hv.w;
    #pragma unroll
    for (int o = 16; o; o >>= 1) {
        s  += __shfl_xor_sync(0xffffffffu, s,  o);
        ss += __shfl_xor_sync(0xffffffffu, ss, o);
    }
    int w = tid >> 5;
    if ((tid & 31) == 0) { ws[w] = s; wss[w] = ss; }
    __syncthreads();

    float ts = 0.f, tss = 0.f;
    #pragma unroll
    for (int i = 0; i < 8; i++) { ts += ws[i]; tss += wss[i]; }
    float mean = ts * (1.f / 1024.f);
    float var  = tss * (1.f / 1024.f) - mean * mean;
    float rstd = rsqrtf(var + 1e-5f);

    float4 g  = ((const float4*)gamma)[tid];
    float4 be = ((const float4*)beta)[tid];
    float4 o;
    o.x = (hv.x - mean) * rstd * g.x + be.x;
    o.y = (hv.y - mean) * rstd * g.y + be.y;
    o.z = (hv.z - mean) * rstd * g.z + be.z;
    o.w = (hv.w - mean) * rstd * g.w + be.w;
    ((float4*)out)[(size_t)row * 256 + tid] = o;
}

// ---------------- launch ------------------------------------------------------
extern "C" void kernel_launch(void* const* d_in, const int* in_sizes, int n_in,
                              void* d_out, int out_size)
{
    const float* x     = (const float*)d_in[0];
    const float* wq    = (const float*)d_in[1];
    const float* bq    = (const float*)d_in[2];
    const float* wk    = (const float*)d_in[3];
    const float* bk    = (const float*)d_in[4];
    const float* wv    = (const float*)d_in[5];
    const float* bv    = (const float*)d_in[6];
    const float* wo    = (const float*)d_in[7];
    const float* bo    = (const float*)d_in[8];
    const float* gamma = (const float*)d_in[9];
    const float* beta  = (const float*)d_in[10];
    const float* pe    = (const float*)d_in[11];
    float* out = (float*)d_out;

    void *pxh, *pqh, *pkh, *pvh, *pah, *pproj, *pwTh;
    cudaGetSymbolAddress(&pxh,   g_xh);
    cudaGetSymbolAddress(&pqh,   g_qh);
    cudaGetSymbolAddress(&pkh,   g_kh);
    cudaGetSymbolAddress(&pvh,   g_vh);
    cudaGetSymbolAddress(&pah,   g_ah);
    cudaGetSymbolAddress(&pproj, g_proj);
    cudaGetSymbolAddress(&pwTh,  g_wTh);
    __half* wTh = (__half*)pwTh;

    cudaFuncSetAttribute(k_gemm_h<__half>, cudaFuncAttributeMaxDynamicSharedMemorySize, GSMEM);
    cudaFuncSetAttribute(k_gemm_h<float>,  cudaFuncAttributeMaxDynamicSharedMemorySize, GSMEM);
    cudaFuncSetAttribute(k_attn_h, cudaFuncAttributeMaxDynamicSharedMemorySize, ASMEM);

    k_addpe<<<(NTOK * DIM / 4) / 256, 256>>>(x, pe);

    dim3 tgrid(DIM / 32, DIM / 32, 4);
    k_transpose4<<<tgrid, 256>>>(wq, wk, wv, wo);

    dim3 ggrid(DIM / 128, NTOK / 128);           // (8, 64)
    k_gemm_h<__half><<<ggrid, 256, GSMEM>>>((const __half*)pxh, wTh + 0 * DIM * DIM, bq, (__half*)pqh);
    k_gemm_h<__half><<<ggrid, 256, GSMEM>>>((const __half*)pxh, wTh + 1 * DIM * DIM, bk, (__half*)pkh);
    k_gemm_h<__half><<<ggrid, 256, GSMEM>>>((const __half*)pxh, wTh + 2 * DIM * DIM, bv, (__half*)pvh);

    dim3 agrid(SEQ / 128, NH, BATCH);            // (16, 16, 4)
    k_attn_h<<<agrid, 256, ASMEM>>>();

    k_gemm_h<float><<<ggrid, 256, GSMEM>>>((const __half*)pah, wTh + 3 * DIM * DIM, bo, (float*)pproj);

    k_ln<<<NTOK, 256>>>(gamma, beta, out);
}